// round 2
// baseline (speedup 1.0000x reference)
#include <cuda_runtime.h>

// DSAttention: causal attention with tau/delta pre-scale.
// B=2, L=S=2048, H=8, E=64 (hard-coded).
// out[b,l,h,:] = softmax_s( scale*(q.k*tau[b] + delta[b,s]) , s<=l ) @ V

#define BM 64
#define BN 64
#define ED 64
#define LDSR 68                 // padded row length (floats)
#define TILE_F (BM * LDSR)      // 4352 floats per tile buffer
#define SMEM_FLOATS (4 * TILE_F + 64)
#define SMEM_BYTES (SMEM_FLOATS * 4)

__global__ __launch_bounds__(256, 1)
void dsattn_kernel(const float* __restrict__ Qg, const float* __restrict__ Kg,
                   const float* __restrict__ Vg, const float* __restrict__ Taug,
                   const float* __restrict__ Dg, float* __restrict__ Og)
{
    const int L = 2048, H = 8;
    const float scale = 0.125f;   // 1/sqrt(64)

    const int mtile = blockIdx.x;   // 0..31 query tile
    const int h     = blockIdx.y;   // 0..7
    const int b     = blockIdx.z;   // 0..1

    const int tid = threadIdx.x;
    const int tx  = tid & 15;       // 0..15 -> score cols n = tx*4+j
    const int ty  = tid >> 4;       // 0..15 -> score rows m = ty*4+i

    extern __shared__ float smem[];
    float* sQ = smem;
    float* sK = sQ + TILE_F;
    float* sV = sK + TILE_F;
    float* sP = sV + TILE_F;
    float* sD = sP + TILE_F;        // 64 floats (scaled delta)

    const float ts = Taug[b] * scale;

    // ---- load Q tile (64 rows x 64) ----
    {
        const int qbase_row = mtile * BM;
        #pragma unroll
        for (int it = 0; it < 4; ++it) {
            int t  = tid + it * 256;          // 0..1023
            int r  = t >> 4;                  // row 0..63
            int c4 = t & 15;                  // float4 index 0..15
            const float4* gp = (const float4*)(Qg + (((size_t)(b * L + qbase_row + r)) * H + h) * ED);
            *((float4*)(sQ + r * LDSR) + c4) = gp[c4];
        }
    }

    // online-softmax state
    float m_i[4], l_i[4], Oacc[16];
    #pragma unroll
    for (int i = 0; i < 4; ++i) { m_i[i] = -1e30f; l_i[i] = 0.f; }
    #pragma unroll
    for (int i = 0; i < 16; ++i) Oacc[i] = 0.f;

    const float* qbase = sQ + (ty * 4) * LDSR;
    const float* kbase = sK + (tx * 4) * LDSR;
    const float* pbase = sP + (ty * 4) * LDSR;

    for (int kt = 0; kt <= mtile; ++kt) {
        __syncthreads();   // protect sK/sV from previous iteration's readers

        // ---- load K, V tile + delta ----
        {
            const int kbase_row = kt * BN;
            #pragma unroll
            for (int it = 0; it < 4; ++it) {
                int t  = tid + it * 256;
                int r  = t >> 4;
                int c4 = t & 15;
                size_t grow = (((size_t)(b * L + kbase_row + r)) * H + h) * ED;
                *((float4*)(sK + r * LDSR) + c4) = ((const float4*)(Kg + grow))[c4];
                *((float4*)(sV + r * LDSR) + c4) = ((const float4*)(Vg + grow))[c4];
            }
            if (tid < 64) sD[tid] = Dg[b * 2048 + kbase_row + tid] * scale;
        }
        __syncthreads();

        // ---- scores: S = (Q.K)*ts + delta ----
        float acc[16];
        #pragma unroll
        for (int i = 0; i < 16; ++i) acc[i] = 0.f;

        #pragma unroll
        for (int e0 = 0; e0 < ED; e0 += 4) {
            float4 qv0 = *(const float4*)(qbase + 0 * LDSR + e0);
            float4 qv1 = *(const float4*)(qbase + 1 * LDSR + e0);
            float4 qv2 = *(const float4*)(qbase + 2 * LDSR + e0);
            float4 qv3 = *(const float4*)(qbase + 3 * LDSR + e0);
            float4 kv0 = *(const float4*)(kbase + 0 * LDSR + e0);
            float4 kv1 = *(const float4*)(kbase + 1 * LDSR + e0);
            float4 kv2 = *(const float4*)(kbase + 2 * LDSR + e0);
            float4 kv3 = *(const float4*)(kbase + 3 * LDSR + e0);
            float4 qv[4] = {qv0, qv1, qv2, qv3};
            float4 kv[4] = {kv0, kv1, kv2, kv3};
            #pragma unroll
            for (int i = 0; i < 4; ++i) {
                #pragma unroll
                for (int j = 0; j < 4; ++j) {
                    acc[i * 4 + j] += qv[i].x * kv[j].x + qv[i].y * kv[j].y
                                    + qv[i].z * kv[j].z + qv[i].w * kv[j].w;
                }
            }
        }

        const bool diag = (kt == mtile);
        float sc[16];
        #pragma unroll
        for (int i = 0; i < 4; ++i) {
            int m = ty * 4 + i;
            #pragma unroll
            for (int j = 0; j < 4; ++j) {
                int n = tx * 4 + j;
                float v = acc[i * 4 + j] * ts + sD[n];
                if (diag && n > m) v = -1e30f;
                sc[i * 4 + j] = v;
            }
        }

        // ---- online softmax per row ----
        #pragma unroll
        for (int i = 0; i < 4; ++i) {
            float mx = fmaxf(fmaxf(sc[i*4+0], sc[i*4+1]), fmaxf(sc[i*4+2], sc[i*4+3]));
            #pragma unroll
            for (int off = 8; off > 0; off >>= 1)
                mx = fmaxf(mx, __shfl_xor_sync(0xffffffffu, mx, off));
            float mnew  = fmaxf(m_i[i], mx);
            float alpha = __expf(m_i[i] - mnew);
            float psum = 0.f;
            #pragma unroll
            for (int j = 0; j < 4; ++j) {
                float p = __expf(sc[i*4+j] - mnew);
                sc[i*4+j] = p;
                psum += p;
            }
            #pragma unroll
            for (int off = 8; off > 0; off >>= 1)
                psum += __shfl_xor_sync(0xffffffffu, psum, off);
            l_i[i] = l_i[i] * alpha + psum;
            m_i[i] = mnew;
            #pragma unroll
            for (int j = 0; j < 4; ++j) Oacc[i*4+j] *= alpha;
            // write P row fragment
            *(float4*)(sP + (ty * 4 + i) * LDSR + tx * 4) =
                make_float4(sc[i*4+0], sc[i*4+1], sc[i*4+2], sc[i*4+3]);
        }
        __syncthreads();

        // ---- O += P @ V ----
        #pragma unroll 4
        for (int n0 = 0; n0 < BN; n0 += 4) {
            float4 pr0 = *(const float4*)(pbase + 0 * LDSR + n0);
            float4 pr1 = *(const float4*)(pbase + 1 * LDSR + n0);
            float4 pr2 = *(const float4*)(pbase + 2 * LDSR + n0);
            float4 pr3 = *(const float4*)(pbase + 3 * LDSR + n0);
            float4 v0 = *(const float4*)(sV + (n0 + 0) * LDSR + tx * 4);
            float4 v1 = *(const float4*)(sV + (n0 + 1) * LDSR + tx * 4);
            float4 v2 = *(const float4*)(sV + (n0 + 2) * LDSR + tx * 4);
            float4 v3 = *(const float4*)(sV + (n0 + 3) * LDSR + tx * 4);
            float4 pr[4] = {pr0, pr1, pr2, pr3};
            #pragma unroll
            for (int i = 0; i < 4; ++i) {
                Oacc[i*4+0] += pr[i].x * v0.x + pr[i].y * v1.x + pr[i].z * v2.x + pr[i].w * v3.x;
                Oacc[i*4+1] += pr[i].x * v0.y + pr[i].y * v1.y + pr[i].z * v2.y + pr[i].w * v3.y;
                Oacc[i*4+2] += pr[i].x * v0.z + pr[i].y * v1.z + pr[i].z * v2.z + pr[i].w * v3.z;
                Oacc[i*4+3] += pr[i].x * v0.w + pr[i].y * v1.w + pr[i].z * v2.w + pr[i].w * v3.w;
            }
        }
    }

    // ---- finalize & write ----
    #pragma unroll
    for (int i = 0; i < 4; ++i) {
        int qi = mtile * BM + ty * 4 + i;
        float inv = 1.0f / l_i[i];
        float4 o = make_float4(Oacc[i*4+0] * inv, Oacc[i*4+1] * inv,
                               Oacc[i*4+2] * inv, Oacc[i*4+3] * inv);
        *(float4*)(Og + (((size_t)(b * L + qi)) * H + h) * ED + tx * 4) = o;
    }
}

extern "C" void kernel_launch(void* const* d_in, const int* in_sizes, int n_in,
                              void* d_out, int out_size)
{
    const float* Q     = (const float*)d_in[0];
    const float* K     = (const float*)d_in[1];
    const float* V     = (const float*)d_in[2];
    const float* tau   = (const float*)d_in[3];
    const float* delta = (const float*)d_in[4];
    float* out = (float*)d_out;

    cudaFuncSetAttribute(dsattn_kernel,
                         cudaFuncAttributeMaxDynamicSharedMemorySize, SMEM_BYTES);

    dim3 grid(32, 8, 2);   // (L/64, H, B)
    dsattn_kernel<<<grid, 256, SMEM_BYTES>>>(Q, K, V, tau, delta, out);
}

// round 7
// speedup vs baseline: 4.3400x; 4.3400x over previous
#include <cuda_runtime.h>
#include <cstdint>

// DSAttention via tf32 tensor-core flash attention.
// B=2, L=S=2048, H=8, E=64. Causal, tau/delta pre-scale.
// BM=128 (8 warps x 16 rows), BN=64, E=64.

#define LQ 2048
#define HH 8
#define BM 128
#define BN 64
#define ED 64
#define KSTR 68     // sK row stride (floats): bank = lane for frag loads
#define VSTR 72     // sV row stride: conflict-free for V B-frags
#define PSTR 68     // sP/sQ row stride

#define SK_F   (64 * KSTR)        // 4352
#define SV_F   (64 * VSTR)        // 4608
#define SQP_F  (128 * PSTR)       // 8704
#define SMEM_FLOATS (SK_F + SV_F + SQP_F + 64)
#define SMEM_BYTES  (SMEM_FLOATS * 4)

__device__ __forceinline__ float tf32r(float x) {
    uint32_t u;
    asm("cvt.rna.tf32.f32 %0, %1;" : "=r"(u) : "f"(x));
    return __uint_as_float(u);
}

__device__ __forceinline__ void mma_tf32(float* d, const uint32_t* a,
                                         uint32_t b0, uint32_t b1) {
    asm volatile(
        "mma.sync.aligned.m16n8k8.row.col.f32.tf32.tf32.f32 "
        "{%0,%1,%2,%3}, {%4,%5,%6,%7}, {%8,%9}, {%0,%1,%2,%3};"
        : "+f"(d[0]), "+f"(d[1]), "+f"(d[2]), "+f"(d[3])
        : "r"(a[0]), "r"(a[1]), "r"(a[2]), "r"(a[3]), "r"(b0), "r"(b1));
}

__global__ __launch_bounds__(256, 1)
void dsattn_tc(const float* __restrict__ Qg, const float* __restrict__ Kg,
               const float* __restrict__ Vg, const float* __restrict__ Taug,
               const float* __restrict__ Dg, float* __restrict__ Og)
{
    const float scale = 0.125f;

    // heavy (large mtile) CTAs first to reduce wave-2 tail
    const int mtile = (int)gridDim.x - 1 - (int)blockIdx.x;   // 0..15
    const int h     = blockIdx.y;
    const int b     = blockIdx.z;

    const int tid  = threadIdx.x;
    const int wid  = tid >> 5;        // 0..7
    const int lane = tid & 31;
    const int g    = lane >> 2;       // group 0..7 (row within tile)
    const int t4   = lane & 3;        // 0..3

    extern __shared__ float smem[];
    float* sK  = smem;                // [64][68]  tf32 bits
    float* sV  = sK + SK_F;           // [64][72]  tf32 bits
    float* sQP = sV + SV_F;           // [128][68] Q staging, then P
    float* sD  = sQP + SQP_F;         // [64] scaled delta

    const float ts = Taug[b] * scale;
    const int wrow = wid * 16;        // this warp's first row in the tile

    // ---- stage Q tile (128 x 64) into sQP, tf32-converted ----
    {
        const int q0 = mtile * BM;
        #pragma unroll
        for (int it = 0; it < 8; ++it) {
            int t  = tid + it * 256;    // 0..2047
            int r  = t >> 4;
            int c4 = t & 15;
            float4 v = ((const float4*)(Qg + (((size_t)(b * LQ + q0 + r)) * HH + h) * ED))[c4];
            v.x = tf32r(v.x); v.y = tf32r(v.y); v.z = tf32r(v.z); v.w = tf32r(v.w);
            *(float4*)(sQP + r * PSTR + c4 * 4) = v;
        }
    }
    __syncthreads();

    // ---- load Q fragments into registers (warp-local rows) ----
    uint32_t qa[8][4];
    {
        const float* qb = sQP + (wrow + g) * PSTR;
        #pragma unroll
        for (int k = 0; k < 8; ++k) {
            qa[k][0] = __float_as_uint(qb[8 * k + t4]);
            qa[k][1] = __float_as_uint(qb[8 * PSTR + 8 * k + t4]);
            qa[k][2] = __float_as_uint(qb[8 * k + t4 + 4]);
            qa[k][3] = __float_as_uint(qb[8 * PSTR + 8 * k + t4 + 4]);
        }
    }

    // online softmax state: two rows per thread (g and g+8 within warp tile)
    float m_i[2] = {-1e30f, -1e30f};
    float l_i[2] = {0.f, 0.f};
    float Oacc[8][4];
    #pragma unroll
    for (int j = 0; j < 8; ++j)
        #pragma unroll
        for (int i = 0; i < 4; ++i) Oacc[j][i] = 0.f;

    const int row0 = mtile * BM + wrow + g;   // global row for c0/c1
    const int row1 = row0 + 8;                // global row for c2/c3
    const int nkt  = 2 * mtile + 2;

    for (int kt = 0; kt < nkt; ++kt) {
        __syncthreads();   // previous iteration's PV / frag reads done

        // ---- load K,V tile (64 x 64) + delta, tf32-converted ----
        {
            const int kr0 = kt * BN;
            #pragma unroll
            for (int it = 0; it < 4; ++it) {
                int t  = tid + it * 256;   // 0..1023
                int r  = t >> 4;
                int c4 = t & 15;
                size_t grow = (((size_t)(b * LQ + kr0 + r)) * HH + h) * ED;
                float4 kv = ((const float4*)(Kg + grow))[c4];
                float4 vv = ((const float4*)(Vg + grow))[c4];
                kv.x = tf32r(kv.x); kv.y = tf32r(kv.y); kv.z = tf32r(kv.z); kv.w = tf32r(kv.w);
                vv.x = tf32r(vv.x); vv.y = tf32r(vv.y); vv.z = tf32r(vv.z); vv.w = tf32r(vv.w);
                *(float4*)(sK + r * KSTR + c4 * 4) = kv;
                *(float4*)(sV + r * VSTR + c4 * 4) = vv;
            }
            if (tid < 64) sD[tid] = Dg[b * LQ + kt * BN + tid] * scale;
        }
        __syncthreads();

        // ---- S = Q @ K^T (tensor cores) ----
        float Sacc[8][4];
        #pragma unroll
        for (int j = 0; j < 8; ++j)
            #pragma unroll
            for (int i = 0; i < 4; ++i) Sacc[j][i] = 0.f;

        #pragma unroll
        for (int k = 0; k < 8; ++k) {
            #pragma unroll
            for (int j = 0; j < 8; ++j) {
                const float* kp = sK + (8 * j + g) * KSTR + 8 * k + t4;
                uint32_t b0 = __float_as_uint(kp[0]);
                uint32_t b1 = __float_as_uint(kp[4]);
                mma_tf32(Sacc[j], qa[k], b0, b1);
            }
        }

        // ---- scale + delta + causal mask ----
        const int cb = kt * BN + 2 * t4;
        #pragma unroll
        for (int j = 0; j < 8; ++j) {
            int c0 = cb + 8 * j;
            float2 d = *(const float2*)(sD + 8 * j + 2 * t4);
            float s0 = Sacc[j][0] * ts + d.x;
            float s1 = Sacc[j][1] * ts + d.y;
            float s2 = Sacc[j][2] * ts + d.x;
            float s3 = Sacc[j][3] * ts + d.y;
            if (c0     > row0) s0 = -1e30f;
            if (c0 + 1 > row0) s1 = -1e30f;
            if (c0     > row1) s2 = -1e30f;
            if (c0 + 1 > row1) s3 = -1e30f;
            Sacc[j][0] = s0; Sacc[j][1] = s1; Sacc[j][2] = s2; Sacc[j][3] = s3;
        }

        // ---- online softmax (two rows per thread, quad-shuffle reductions) ----
        #pragma unroll
        for (int hh = 0; hh < 2; ++hh) {
            float mx = -1e30f;
            #pragma unroll
            for (int j = 0; j < 8; ++j)
                mx = fmaxf(mx, fmaxf(Sacc[j][2 * hh], Sacc[j][2 * hh + 1]));
            mx = fmaxf(mx, __shfl_xor_sync(0xffffffffu, mx, 1));
            mx = fmaxf(mx, __shfl_xor_sync(0xffffffffu, mx, 2));
            float mnew  = fmaxf(m_i[hh], mx);
            float alpha = __expf(m_i[hh] - mnew);
            float psum = 0.f;
            const int prow = wrow + g + 8 * hh;
            #pragma unroll
            for (int j = 0; j < 8; ++j) {
                float p0 = __expf(Sacc[j][2 * hh]     - mnew);
                float p1 = __expf(Sacc[j][2 * hh + 1] - mnew);
                psum += p0 + p1;
                float2 pv;
                pv.x = tf32r(p0);
                pv.y = tf32r(p1);
                *(float2*)(sQP + prow * PSTR + 8 * j + 2 * t4) = pv;
            }
            psum += __shfl_xor_sync(0xffffffffu, psum, 1);
            psum += __shfl_xor_sync(0xffffffffu, psum, 2);
            l_i[hh] = l_i[hh] * alpha + psum;
            m_i[hh] = mnew;
            #pragma unroll
            for (int j = 0; j < 8; ++j) {
                Oacc[j][2 * hh]     *= alpha;
                Oacc[j][2 * hh + 1] *= alpha;
            }
        }
        __syncwarp();   // P round-trip is warp-local (each warp reads only its own rows)

        // ---- O += P @ V (tensor cores) ----
        #pragma unroll
        for (int k = 0; k < 8; ++k) {
            const float* pr = sQP + (wrow + g) * PSTR + 8 * k;
            uint32_t pa[4];
            pa[0] = __float_as_uint(pr[t4]);
            pa[1] = __float_as_uint(pr[8 * PSTR + t4]);
            pa[2] = __float_as_uint(pr[t4 + 4]);
            pa[3] = __float_as_uint(pr[8 * PSTR + t4 + 4]);
            #pragma unroll
            for (int j = 0; j < 8; ++j) {
                const float* vp = sV + (8 * k + t4) * VSTR + 8 * j + g;
                uint32_t b0 = __float_as_uint(vp[0]);
                uint32_t b1 = __float_as_uint(vp[4 * VSTR]);
                mma_tf32(Oacc[j], pa, b0, b1);
            }
        }
    }

    // ---- finalize & write ----
    {
        float inv0 = 1.0f / l_i[0];
        float inv1 = 1.0f / l_i[1];
        float* o0 = Og + (((size_t)(b * LQ + row0)) * HH + h) * ED;
        float* o1 = Og + (((size_t)(b * LQ + row1)) * HH + h) * ED;
        #pragma unroll
        for (int j = 0; j < 8; ++j) {
            int e = 8 * j + 2 * t4;
            *(float2*)(o0 + e) = make_float2(Oacc[j][0] * inv0, Oacc[j][1] * inv0);
            *(float2*)(o1 + e) = make_float2(Oacc[j][2] * inv1, Oacc[j][3] * inv1);
        }
    }
}

extern "C" void kernel_launch(void* const* d_in, const int* in_sizes, int n_in,
                              void* d_out, int out_size)
{
    const float* Q     = (const float*)d_in[0];
    const float* K     = (const float*)d_in[1];
    const float* V     = (const float*)d_in[2];
    const float* tau   = (const float*)d_in[3];
    const float* delta = (const float*)d_in[4];
    float* out = (float*)d_out;

    cudaFuncSetAttribute(dsattn_tc,
                         cudaFuncAttributeMaxDynamicSharedMemorySize, SMEM_BYTES);

    dim3 grid(LQ / BM, HH, 2);   // (16, 8, 2)
    dsattn_tc<<<grid, 256, SMEM_BYTES>>>(Q, K, V, tau, delta, out);
}

// round 9
// speedup vs baseline: 5.5434x; 1.2773x over previous
#include <cuda_runtime.h>
#include <cstdint>

// DSAttention via tf32 tensor-core flash attention.
// B=2, L=S=2048, H=8, E=64. Causal, tau/delta pre-scale.
// BM=64 (4 warps x 16 rows), BN=64, E=64. 128 threads/CTA -> 3 CTAs/SM.

#define LQ 2048
#define HH 8
#define BM 64
#define BN 64
#define ED 64
#define NTHREADS 128
#define KSTR 68     // sK row stride (floats): conflict-free frag loads
#define VSTR 72     // sV row stride: conflict-free for V B-frags
#define PSTR 68     // sP/sQ row stride

#define SK_F   (64 * KSTR)        // 4352
#define SV_F   (64 * VSTR)        // 4608
#define SQP_F  (BM * PSTR)        // 4352
#define SMEM_FLOATS (SK_F + SV_F + SQP_F + 64)
#define SMEM_BYTES  (SMEM_FLOATS * 4)

__device__ __forceinline__ float tf32r(float x) {
    uint32_t u;
    asm("cvt.rna.tf32.f32 %0, %1;" : "=r"(u) : "f"(x));
    return __uint_as_float(u);
}

__device__ __forceinline__ void mma_tf32(float* d, const uint32_t* a,
                                         uint32_t b0, uint32_t b1) {
    asm volatile(
        "mma.sync.aligned.m16n8k8.row.col.f32.tf32.tf32.f32 "
        "{%0,%1,%2,%3}, {%4,%5,%6,%7}, {%8,%9}, {%0,%1,%2,%3};"
        : "+f"(d[0]), "+f"(d[1]), "+f"(d[2]), "+f"(d[3])
        : "r"(a[0]), "r"(a[1]), "r"(a[2]), "r"(a[3]), "r"(b0), "r"(b1));
}

__global__ __launch_bounds__(NTHREADS)
void dsattn_tc(const float* __restrict__ Qg, const float* __restrict__ Kg,
               const float* __restrict__ Vg, const float* __restrict__ Taug,
               const float* __restrict__ Dg, float* __restrict__ Og)
{
    const float scale = 0.125f;

    // heavy (large mtile) CTAs first to reduce wave tail
    const int mtile = (int)gridDim.x - 1 - (int)blockIdx.x;   // 0..31
    const int h     = blockIdx.y;
    const int b     = blockIdx.z;

    const int tid  = threadIdx.x;
    const int wid  = tid >> 5;        // 0..3
    const int lane = tid & 31;
    const int g    = lane >> 2;       // group 0..7 (row within warp tile)
    const int t4   = lane & 3;        // 0..3

    extern __shared__ float smem[];
    float* sK  = smem;                // [64][68]  tf32 bits
    float* sV  = sK + SK_F;           // [64][72]  tf32 bits
    float* sQP = sV + SV_F;           // [64][68]  Q staging, then P
    float* sD  = sQP + SQP_F;         // [64] scaled delta

    const float ts = Taug[b] * scale;
    const int wrow = wid * 16;        // this warp's first row in the tile

    // ---- stage Q tile (64 x 64) into sQP, tf32-converted ----
    {
        const int q0 = mtile * BM;
        #pragma unroll
        for (int it = 0; it < 8; ++it) {
            int t  = tid + it * NTHREADS;   // 0..1023
            int r  = t >> 4;
            int c4 = t & 15;
            float4 v = ((const float4*)(Qg + (((size_t)(b * LQ + q0 + r)) * HH + h) * ED))[c4];
            v.x = tf32r(v.x); v.y = tf32r(v.y); v.z = tf32r(v.z); v.w = tf32r(v.w);
            *(float4*)(sQP + r * PSTR + c4 * 4) = v;
        }
    }
    __syncthreads();

    // ---- load Q fragments into registers (warp-local rows) ----
    uint32_t qa[8][4];
    {
        const float* qb = sQP + (wrow + g) * PSTR;
        #pragma unroll
        for (int k = 0; k < 8; ++k) {
            qa[k][0] = __float_as_uint(qb[8 * k + t4]);
            qa[k][1] = __float_as_uint(qb[8 * PSTR + 8 * k + t4]);
            qa[k][2] = __float_as_uint(qb[8 * k + t4 + 4]);
            qa[k][3] = __float_as_uint(qb[8 * PSTR + 8 * k + t4 + 4]);
        }
    }

    // online softmax state: two rows per thread (g and g+8 within warp tile)
    float m_i[2] = {-1e30f, -1e30f};
    float l_i[2] = {0.f, 0.f};
    float Oacc[8][4];
    #pragma unroll
    for (int j = 0; j < 8; ++j)
        #pragma unroll
        for (int i = 0; i < 4; ++i) Oacc[j][i] = 0.f;

    const int row0 = mtile * BM + wrow + g;   // global row for c0/c1
    const int row1 = row0 + 8;                // global row for c2/c3
    const int nkt  = mtile + 1;

    for (int kt = 0; kt < nkt; ++kt) {
        __syncthreads();   // previous iteration's PV / frag reads done

        // ---- load K,V tile (64 x 64) + delta, tf32-converted ----
        {
            const int kr0 = kt * BN;
            #pragma unroll
            for (int it = 0; it < 8; ++it) {
                int t  = tid + it * NTHREADS;   // 0..1023
                int r  = t >> 4;
                int c4 = t & 15;
                size_t grow = (((size_t)(b * LQ + kr0 + r)) * HH + h) * ED;
                float4 kv = ((const float4*)(Kg + grow))[c4];
                float4 vv = ((const float4*)(Vg + grow))[c4];
                kv.x = tf32r(kv.x); kv.y = tf32r(kv.y); kv.z = tf32r(kv.z); kv.w = tf32r(kv.w);
                vv.x = tf32r(vv.x); vv.y = tf32r(vv.y); vv.z = tf32r(vv.z); vv.w = tf32r(vv.w);
                *(float4*)(sK + r * KSTR + c4 * 4) = kv;
                *(float4*)(sV + r * VSTR + c4 * 4) = vv;
            }
            if (tid < 64) sD[tid] = Dg[b * LQ + kt * BN + tid] * scale;
        }
        __syncthreads();

        // ---- S = Q @ K^T (tensor cores) ----
        float Sacc[8][4];
        #pragma unroll
        for (int j = 0; j < 8; ++j)
            #pragma unroll
            for (int i = 0; i < 4; ++i) Sacc[j][i] = 0.f;

        #pragma unroll
        for (int k = 0; k < 8; ++k) {
            #pragma unroll
            for (int j = 0; j < 8; ++j) {
                const float* kp = sK + (8 * j + g) * KSTR + 8 * k + t4;
                uint32_t b0 = __float_as_uint(kp[0]);
                uint32_t b1 = __float_as_uint(kp[4]);
                mma_tf32(Sacc[j], qa[k], b0, b1);
            }
        }

        // ---- scale + delta + causal mask ----
        const int cb = kt * BN + 2 * t4;
        #pragma unroll
        for (int j = 0; j < 8; ++j) {
            int c0 = cb + 8 * j;
            float2 d = *(const float2*)(sD + 8 * j + 2 * t4);
            float s0 = Sacc[j][0] * ts + d.x;
            float s1 = Sacc[j][1] * ts + d.y;
            float s2 = Sacc[j][2] * ts + d.x;
            float s3 = Sacc[j][3] * ts + d.y;
            if (c0     > row0) s0 = -1e30f;
            if (c0 + 1 > row0) s1 = -1e30f;
            if (c0     > row1) s2 = -1e30f;
            if (c0 + 1 > row1) s3 = -1e30f;
            Sacc[j][0] = s0; Sacc[j][1] = s1; Sacc[j][2] = s2; Sacc[j][3] = s3;
        }

        // ---- online softmax (two rows per thread, quad-shuffle reductions) ----
        #pragma unroll
        for (int hh = 0; hh < 2; ++hh) {
            float mx = -1e30f;
            #pragma unroll
            for (int j = 0; j < 8; ++j)
                mx = fmaxf(mx, fmaxf(Sacc[j][2 * hh], Sacc[j][2 * hh + 1]));
            mx = fmaxf(mx, __shfl_xor_sync(0xffffffffu, mx, 1));
            mx = fmaxf(mx, __shfl_xor_sync(0xffffffffu, mx, 2));
            float mnew  = fmaxf(m_i[hh], mx);
            float alpha = __expf(m_i[hh] - mnew);
            float psum = 0.f;
            const int prow = wrow + g + 8 * hh;
            #pragma unroll
            for (int j = 0; j < 8; ++j) {
                float p0 = __expf(Sacc[j][2 * hh]     - mnew);
                float p1 = __expf(Sacc[j][2 * hh + 1] - mnew);
                psum += p0 + p1;
                float2 pv;
                pv.x = tf32r(p0);
                pv.y = tf32r(p1);
                *(float2*)(sQP + prow * PSTR + 8 * j + 2 * t4) = pv;
            }
            psum += __shfl_xor_sync(0xffffffffu, psum, 1);
            psum += __shfl_xor_sync(0xffffffffu, psum, 2);
            l_i[hh] = l_i[hh] * alpha + psum;
            m_i[hh] = mnew;
            #pragma unroll
            for (int j = 0; j < 8; ++j) {
                Oacc[j][2 * hh]     *= alpha;
                Oacc[j][2 * hh + 1] *= alpha;
            }
        }
        __syncwarp();   // P round-trip is warp-local (each warp reads only its own rows)

        // ---- O += P @ V (tensor cores) ----
        #pragma unroll
        for (int k = 0; k < 8; ++k) {
            const float* pr = sQP + (wrow + g) * PSTR + 8 * k;
            uint32_t pa[4];
            pa[0] = __float_as_uint(pr[t4]);
            pa[1] = __float_as_uint(pr[8 * PSTR + t4]);
            pa[2] = __float_as_uint(pr[t4 + 4]);
            pa[3] = __float_as_uint(pr[8 * PSTR + t4 + 4]);
            #pragma unroll
            for (int j = 0; j < 8; ++j) {
                const float* vp = sV + (8 * k + t4) * VSTR + 8 * j + g;
                uint32_t b0 = __float_as_uint(vp[0]);
                uint32_t b1 = __float_as_uint(vp[4 * VSTR]);
                mma_tf32(Oacc[j], pa, b0, b1);
            }
        }
    }

    // ---- finalize & write ----
    {
        float inv0 = 1.0f / l_i[0];
        float inv1 = 1.0f / l_i[1];
        float* o0 = Og + (((size_t)(b * LQ + row0)) * HH + h) * ED;
        float* o1 = Og + (((size_t)(b * LQ + row1)) * HH + h) * ED;
        #pragma unroll
        for (int j = 0; j < 8; ++j) {
            int e = 8 * j + 2 * t4;
            *(float2*)(o0 + e) = make_float2(Oacc[j][0] * inv0, Oacc[j][1] * inv0);
            *(float2*)(o1 + e) = make_float2(Oacc[j][2] * inv1, Oacc[j][3] * inv1);
        }
    }
}

extern "C" void kernel_launch(void* const* d_in, const int* in_sizes, int n_in,
                              void* d_out, int out_size)
{
    const float* Q     = (const float*)d_in[0];
    const float* K     = (const float*)d_in[1];
    const float* V     = (const float*)d_in[2];
    const float* tau   = (const float*)d_in[3];
    const float* delta = (const float*)d_in[4];
    float* out = (float*)d_out;

    cudaFuncSetAttribute(dsattn_tc,
                         cudaFuncAttributeMaxDynamicSharedMemorySize, SMEM_BYTES);

    dim3 grid(LQ / BM, HH, 2);   // (32, 8, 2) = 512 CTAs
    dsattn_tc<<<grid, NTHREADS, SMEM_BYTES>>>(Q, K, V, tau, delta, out);
}

// round 10
// speedup vs baseline: 6.5257x; 1.1772x over previous
#include <cuda_runtime.h>
#include <cstdint>

// DSAttention tf32 tensor-core flash attention + cp.async pipeline.
// B=2, L=S=2048, H=8, E=64. Causal, tau/delta pre-scale.
// BM=64 (4 warps x 16 rows), BN=64. 128 threads/CTA, 3 CTAs/SM.
// K double-buffered (prefetch 1 tile ahead), V+delta overlapped with QK+softmax.
// Raw fp32 in smem; tf32 mma truncates mantissa in hardware (no explicit cvt).

#define LQ 2048
#define HH 8
#define BM 64
#define BN 64
#define ED 64
#define NTHREADS 128
#define KSTR 68
#define VSTR 72
#define PSTR 68

#define SK_F   (64 * KSTR)        // 4352 (per buffer)
#define SV_F   (64 * VSTR)        // 4608
#define SQP_F  (BM * PSTR)        // 4352
#define SMEM_FLOATS (2 * SK_F + SV_F + SQP_F + 64)
#define SMEM_BYTES  (SMEM_FLOATS * 4)

__device__ __forceinline__ void cpasync16(uint32_t dst, const void* src) {
    asm volatile("cp.async.cg.shared.global [%0], [%1], 16;" :: "r"(dst), "l"(src));
}
__device__ __forceinline__ void cp_commit() {
    asm volatile("cp.async.commit_group;" ::: "memory");
}
__device__ __forceinline__ void cp_wait1() {
    asm volatile("cp.async.wait_group 1;" ::: "memory");
}
__device__ __forceinline__ void cp_wait0() {
    asm volatile("cp.async.wait_group 0;" ::: "memory");
}

__device__ __forceinline__ void mma_tf32(float* d, const uint32_t* a,
                                         uint32_t b0, uint32_t b1) {
    asm volatile(
        "mma.sync.aligned.m16n8k8.row.col.f32.tf32.tf32.f32 "
        "{%0,%1,%2,%3}, {%4,%5,%6,%7}, {%8,%9}, {%0,%1,%2,%3};"
        : "+f"(d[0]), "+f"(d[1]), "+f"(d[2]), "+f"(d[3])
        : "r"(a[0]), "r"(a[1]), "r"(a[2]), "r"(a[3]), "r"(b0), "r"(b1));
}

__global__ __launch_bounds__(NTHREADS, 3)
void dsattn_tc(const float* __restrict__ Qg, const float* __restrict__ Kg,
               const float* __restrict__ Vg, const float* __restrict__ Taug,
               const float* __restrict__ Dg, float* __restrict__ Og)
{
    const float scale = 0.125f;

    const int mtile = (int)gridDim.x - 1 - (int)blockIdx.x;   // heavy first
    const int h     = blockIdx.y;
    const int b     = blockIdx.z;

    const int tid  = threadIdx.x;
    const int wid  = tid >> 5;
    const int lane = tid & 31;
    const int g    = lane >> 2;
    const int t4   = lane & 3;

    extern __shared__ float smem[];
    float* sK0 = smem;                 // [64][68] x2 buffers
    float* sK1 = sK0 + SK_F;
    float* sV  = sK1 + SK_F;           // [64][72]
    float* sQP = sV + SV_F;            // [64][68] Q staging, then P
    float* sD  = sQP + SQP_F;          // [64] raw delta

    const uint32_t smem_u32 = (uint32_t)__cvta_generic_to_shared(smem);
    const uint32_t sK0u = smem_u32;
    const uint32_t sK1u = sK0u + SK_F * 4;
    const uint32_t sVu  = sK1u + SK_F * 4;
    const uint32_t sQPu = sVu + SV_F * 4;
    const uint32_t sDu  = sQPu + SQP_F * 4;

    const float ts = Taug[b] * scale;
    const int wrow = wid * 16;

    // per-thread chunk coords (16B chunks, 16 per row)
    const int r_lo  = tid >> 4;          // rows covered: r_lo + 8*it? No:
    // t = tid + it*128 -> r = t>>4 = (tid>>4) + it*8 ; c4 = tid & 15
    const int c4    = tid & 15;
    const float* QKVbase_q = Qg + ((size_t)(b * LQ) * HH + h) * ED;
    const float* Kbase     = Kg + ((size_t)(b * LQ) * HH + h) * ED;
    const float* Vbase     = Vg + ((size_t)(b * LQ) * HH + h) * ED;
    const float* Dbase     = Dg + b * LQ;

    // ---- prologue: cp.async Q tile + K tile 0 ----
    {
        const int q0 = mtile * BM;
        #pragma unroll
        for (int it = 0; it < 8; ++it) {
            int r = r_lo + it * 8;
            cpasync16(sQPu + (r * PSTR + c4 * 4) * 4,
                      QKVbase_q + (size_t)(q0 + r) * (HH * ED) + c4 * 4);
            cpasync16(sK0u + (r * KSTR + c4 * 4) * 4,
                      Kbase + (size_t)r * (HH * ED) + c4 * 4);
        }
        cp_commit();
        cp_wait0();
    }
    __syncthreads();

    // ---- Q fragments (raw fp32; mma truncates to tf32) ----
    uint32_t qa[8][4];
    {
        const float* qb = sQP + (wrow + g) * PSTR;
        #pragma unroll
        for (int k = 0; k < 8; ++k) {
            qa[k][0] = __float_as_uint(qb[8 * k + t4]);
            qa[k][1] = __float_as_uint(qb[8 * PSTR + 8 * k + t4]);
            qa[k][2] = __float_as_uint(qb[8 * k + t4 + 4]);
            qa[k][3] = __float_as_uint(qb[8 * PSTR + 8 * k + t4 + 4]);
        }
    }

    float m_i[2] = {-1e30f, -1e30f};
    float l_i[2] = {0.f, 0.f};
    float Oacc[8][4];
    #pragma unroll
    for (int j = 0; j < 8; ++j)
        #pragma unroll
        for (int i = 0; i < 4; ++i) Oacc[j][i] = 0.f;

    const int row0 = mtile * BM + wrow + g;
    const int row1 = row0 + 8;
    const int nkt  = mtile + 1;

    for (int kt = 0; kt < nkt; ++kt) {
        __syncthreads();   // sV/sD free (prev PV done); K[cur] visible

        const float* sK  = (kt & 1) ? sK1 : sK0;
        const uint32_t sKnu = (kt & 1) ? sK0u : sK1u;

        // ---- group A: V(kt) + delta(kt) ----
        {
            const int kr0 = kt * BN;
            #pragma unroll
            for (int it = 0; it < 8; ++it) {
                int r = r_lo + it * 8;
                cpasync16(sVu + (r * VSTR + c4 * 4) * 4,
                          Vbase + (size_t)(kr0 + r) * (HH * ED) + c4 * 4);
            }
            if (tid < 16) cpasync16(sDu + tid * 16, Dbase + kr0 + tid * 4);
            cp_commit();
        }
        // ---- group B: K(kt+1) into other buffer ----
        if (kt + 1 < nkt) {
            const int kr0 = (kt + 1) * BN;
            #pragma unroll
            for (int it = 0; it < 8; ++it) {
                int r = r_lo + it * 8;
                cpasync16(sKnu + (r * KSTR + c4 * 4) * 4,
                          Kbase + (size_t)(kr0 + r) * (HH * ED) + c4 * 4);
            }
        }
        cp_commit();

        // ---- S = Q @ K^T ----
        float Sacc[8][4];
        #pragma unroll
        for (int j = 0; j < 8; ++j)
            #pragma unroll
            for (int i = 0; i < 4; ++i) Sacc[j][i] = 0.f;

        #pragma unroll
        for (int k = 0; k < 8; ++k) {
            #pragma unroll
            for (int j = 0; j < 8; ++j) {
                const float* kp = sK + (8 * j + g) * KSTR + 8 * k + t4;
                uint32_t b0 = __float_as_uint(kp[0]);
                uint32_t b1 = __float_as_uint(kp[4]);
                mma_tf32(Sacc[j], qa[k], b0, b1);
            }
        }

        cp_wait1();        // V + delta ready (K(kt+1) may still be in flight)
        __syncthreads();

        // ---- scale + delta + causal mask ----
        const int cb = kt * BN + 2 * t4;
        #pragma unroll
        for (int j = 0; j < 8; ++j) {
            int c0 = cb + 8 * j;
            float2 d = *(const float2*)(sD + 8 * j + 2 * t4);
            float dx = d.x * scale, dy = d.y * scale;
            float s0 = Sacc[j][0] * ts + dx;
            float s1 = Sacc[j][1] * ts + dy;
            float s2 = Sacc[j][2] * ts + dx;
            float s3 = Sacc[j][3] * ts + dy;
            if (c0     > row0) s0 = -1e30f;
            if (c0 + 1 > row0) s1 = -1e30f;
            if (c0     > row1) s2 = -1e30f;
            if (c0 + 1 > row1) s3 = -1e30f;
            Sacc[j][0] = s0; Sacc[j][1] = s1; Sacc[j][2] = s2; Sacc[j][3] = s3;
        }

        // ---- online softmax ----
        #pragma unroll
        for (int hh = 0; hh < 2; ++hh) {
            float mx = -1e30f;
            #pragma unroll
            for (int j = 0; j < 8; ++j)
                mx = fmaxf(mx, fmaxf(Sacc[j][2 * hh], Sacc[j][2 * hh + 1]));
            mx = fmaxf(mx, __shfl_xor_sync(0xffffffffu, mx, 1));
            mx = fmaxf(mx, __shfl_xor_sync(0xffffffffu, mx, 2));
            float mnew  = fmaxf(m_i[hh], mx);
            float alpha = __expf(m_i[hh] - mnew);
            float psum = 0.f;
            const int prow = wrow + g + 8 * hh;
            #pragma unroll
            for (int j = 0; j < 8; ++j) {
                float p0 = __expf(Sacc[j][2 * hh]     - mnew);
                float p1 = __expf(Sacc[j][2 * hh + 1] - mnew);
                psum += p0 + p1;
                *(float2*)(sQP + prow * PSTR + 8 * j + 2 * t4) = make_float2(p0, p1);
            }
            psum += __shfl_xor_sync(0xffffffffu, psum, 1);
            psum += __shfl_xor_sync(0xffffffffu, psum, 2);
            l_i[hh] = l_i[hh] * alpha + psum;
            m_i[hh] = mnew;
            #pragma unroll
            for (int j = 0; j < 8; ++j) {
                Oacc[j][2 * hh]     *= alpha;
                Oacc[j][2 * hh + 1] *= alpha;
            }
        }
        __syncwarp();   // P round-trip is warp-local

        // ---- O += P @ V ----
        #pragma unroll
        for (int k = 0; k < 8; ++k) {
            const float* pr = sQP + (wrow + g) * PSTR + 8 * k;
            uint32_t pa[4];
            pa[0] = __float_as_uint(pr[t4]);
            pa[1] = __float_as_uint(pr[8 * PSTR + t4]);
            pa[2] = __float_as_uint(pr[t4 + 4]);
            pa[3] = __float_as_uint(pr[8 * PSTR + t4 + 4]);
            #pragma unroll
            for (int j = 0; j < 8; ++j) {
                const float* vp = sV + (8 * k + t4) * VSTR + 8 * j + g;
                uint32_t b0 = __float_as_uint(vp[0]);
                uint32_t b1 = __float_as_uint(vp[4 * VSTR]);
                mma_tf32(Oacc[j], pa, b0, b1);
            }
        }

        cp_wait0();    // K(kt+1) landed; visibility via top-of-loop barrier
    }

    // ---- finalize & write ----
    {
        float inv0 = 1.0f / l_i[0];
        float inv1 = 1.0f / l_i[1];
        float* o0 = Og + (((size_t)(b * LQ + row0)) * HH + h) * ED;
        float* o1 = Og + (((size_t)(b * LQ + row1)) * HH + h) * ED;
        #pragma unroll
        for (int j = 0; j < 8; ++j) {
            int e = 8 * j + 2 * t4;
            *(float2*)(o0 + e) = make_float2(Oacc[j][0] * inv0, Oacc[j][1] * inv0);
            *(float2*)(o1 + e) = make_float2(Oacc[j][2] * inv1, Oacc[j][3] * inv1);
        }
    }
}

extern "C" void kernel_launch(void* const* d_in, const int* in_sizes, int n_in,
                              void* d_out, int out_size)
{
    const float* Q     = (const float*)d_in[0];
    const float* K     = (const float*)d_in[1];
    const float* V     = (const float*)d_in[2];
    const float* tau   = (const float*)d_in[3];
    const float* delta = (const float*)d_in[4];
    float* out = (float*)d_out;

    cudaFuncSetAttribute(dsattn_tc,
                         cudaFuncAttributeMaxDynamicSharedMemorySize, SMEM_BYTES);

    dim3 grid(LQ / BM, HH, 2);   // (32, 8, 2) = 512 CTAs
    dsattn_tc<<<grid, NTHREADS, SMEM_BYTES>>>(Q, K, V, tau, delta, out);
}